// round 3
// baseline (speedup 1.0000x reference)
#include <cuda_runtime.h>
#include <math.h>

#define Bv 2
#define Hv_ 16
#define Sv 2048
#define Dv 64
#define EPS_ADJ 1e-9f
#define NEG_BIG 1e9f

// scratch for avAp [B*H, 64, 64]
__device__ float d_avAp[Bv * Hv_ * Dv * Dv];

// ---------------------------------------------------------------------------
// Stage A: avAp = a @ pow(iswiglu(W @ A + b) + eps, pw) + ba   per (b,h)
// One CTA per (b,h). 256 threads, 4x4 register tiles.
// ---------------------------------------------------------------------------
__global__ __launch_bounds__(256) void plga_stage_a(
    const float* __restrict__ A, const float* __restrict__ W,
    const float* __restrict__ b, const float* __restrict__ pw,
    const float* __restrict__ a, const float* __restrict__ ba)
{
    __shared__ float sL[64 * 64];   // left matrix (W, then a)
    __shared__ float sR[64 * 64];   // right matrix (A)
    __shared__ float sP[64 * 64];   // Ap

    int bh = blockIdx.x;
    int h = bh & (Hv_ - 1);
    int tid = threadIdx.x;
    int tx = tid & 15, ty = tid >> 4;
    int i0 = ty * 4, k0 = tx * 4;

    const float* Ab  = A  + bh * 4096;
    const float* Wh  = W  + h * 4096;
    const float* bhp = b  + h * 4096;
    const float* pwh = pw + h * 4096;
    const float* ah  = a  + h * 4096;
    const float* bah = ba + h * 4096;

    for (int idx = tid; idx < 4096; idx += 256) {
        sR[idx] = Ab[idx];
        sL[idx] = Wh[idx];
    }
    __syncthreads();

    float acc[4][4];
#pragma unroll
    for (int r = 0; r < 4; r++)
#pragma unroll
        for (int c = 0; c < 4; c++) acc[r][c] = 0.f;

#pragma unroll 4
    for (int j = 0; j < 64; j++) {
        float lv[4], rv[4];
#pragma unroll
        for (int r = 0; r < 4; r++) lv[r] = sL[(i0 + r) * 64 + j];
#pragma unroll
        for (int c = 0; c < 4; c++) rv[c] = sR[j * 64 + k0 + c];
#pragma unroll
        for (int r = 0; r < 4; r++)
#pragma unroll
            for (int c = 0; c < 4; c++) acc[r][c] = fmaf(lv[r], rv[c], acc[r][c]);
    }
    __syncthreads();

    // Ap = pow(iswiglu(x)+eps, pw)
#pragma unroll
    for (int r = 0; r < 4; r++)
#pragma unroll
        for (int c = 0; c < 4; c++) {
            int i = i0 + r, k = k0 + c;
            float x = acc[r][c] + bhp[i * 64 + k];
            float sig = 1.f / (1.f + expf(-x));
            float aw = x * x * sig + EPS_ADJ;   // x*silu(x) + eps, > 0
            sP[i * 64 + k] = powf(aw, pwh[i * 64 + k]);
        }

    // load 'a' into sL (all sL reads finished before previous sync)
    for (int idx = tid; idx < 4096; idx += 256) sL[idx] = ah[idx];
    __syncthreads();

#pragma unroll
    for (int r = 0; r < 4; r++)
#pragma unroll
        for (int c = 0; c < 4; c++) acc[r][c] = 0.f;

#pragma unroll 4
    for (int j = 0; j < 64; j++) {
        float lv[4], rv[4];
#pragma unroll
        for (int r = 0; r < 4; r++) lv[r] = sL[(i0 + r) * 64 + j];
#pragma unroll
        for (int c = 0; c < 4; c++) rv[c] = sP[j * 64 + k0 + c];
#pragma unroll
        for (int r = 0; r < 4; r++)
#pragma unroll
            for (int c = 0; c < 4; c++) acc[r][c] = fmaf(lv[r], rv[c], acc[r][c]);
    }

    float* outp = d_avAp + bh * 4096;
#pragma unroll
    for (int r = 0; r < 4; r++)
#pragma unroll
        for (int c = 0; c < 4; c++)
            outp[(i0 + r) * 64 + k0 + c] = acc[r][c] + bah[(i0 + r) * 64 + k0 + c];
}

// ---------------------------------------------------------------------------
// Attention: per CTA one 64-row q tile of one (b,h).
//   prologue: q = (Hin_tile @ avAp) * 1/sqrt(D)
//   loop over kv tiles 0..qt: S = q K^T, causal mask on diagonal,
//   online softmax, O += P V. 256 threads, 4x4 fragments, stride-65 smem.
// ---------------------------------------------------------------------------
#define SSTR 65
#define SMEM_FLOATS (4 * 64 * SSTR)

__global__ __launch_bounds__(256) void plga_attn(
    const float* __restrict__ Hin, const float* __restrict__ Hk,
    const float* __restrict__ Hvv, float* __restrict__ out)
{
    extern __shared__ float smem[];
    float* sQ = smem;                  // [64][65]
    float* sK = smem + 64 * SSTR;      // [64][65] (avAp in prologue)
    float* sV = smem + 2 * 64 * SSTR;  // [64][65] (Hin tile in prologue)
    float* sP = smem + 3 * 64 * SSTR;  // [64][65]

    int bh = blockIdx.y;
    int qt = blockIdx.x;
    int tid = threadIdx.x;
    int tx = tid & 15, ty = tid >> 4;
    int r0 = ty * 4, c0 = tx * 4;

    const float* base_in = Hin + (size_t)bh * Sv * Dv;
    const float* base_k  = Hk  + (size_t)bh * Sv * Dv;
    const float* base_v  = Hvv + (size_t)bh * Sv * Dv;

    // ---- prologue: avAp -> sK, Hin tile -> sV ----
    {
        const float4* a4 = (const float4*)(d_avAp + bh * 4096);
        const float4* h4 = (const float4*)(base_in + qt * 64 * Dv);
        for (int idx = tid; idx < 1024; idx += 256) {
            int r = idx >> 4, c = (idx & 15) << 2;
            float4 v1 = a4[idx];
            float* d1 = &sK[r * SSTR + c];
            d1[0] = v1.x; d1[1] = v1.y; d1[2] = v1.z; d1[3] = v1.w;
            float4 v2 = h4[idx];
            float* d2 = &sV[r * SSTR + c];
            d2[0] = v2.x; d2[1] = v2.y; d2[2] = v2.z; d2[3] = v2.w;
        }
    }
    __syncthreads();
    {
        float acc[4][4];
#pragma unroll
        for (int r = 0; r < 4; r++)
#pragma unroll
            for (int c = 0; c < 4; c++) acc[r][c] = 0.f;
#pragma unroll 8
        for (int i = 0; i < 64; i++) {
            float hvr[4], avv[4];
#pragma unroll
            for (int r = 0; r < 4; r++) hvr[r] = sV[(r0 + r) * SSTR + i];
#pragma unroll
            for (int c = 0; c < 4; c++) avv[c] = sK[i * SSTR + c0 + c];
#pragma unroll
            for (int r = 0; r < 4; r++)
#pragma unroll
                for (int c = 0; c < 4; c++) acc[r][c] = fmaf(hvr[r], avv[c], acc[r][c]);
        }
        // write scaled q fragments (only our own cells; visible after next sync)
#pragma unroll
        for (int r = 0; r < 4; r++)
#pragma unroll
            for (int c = 0; c < 4; c++)
                sQ[(r0 + r) * SSTR + c0 + c] = acc[r][c] * 0.125f;  // 1/sqrt(64)
    }

    float m_i[4], l_i[4], o[4][4];
#pragma unroll
    for (int r = 0; r < 4; r++) {
        m_i[r] = -1e30f;
        l_i[r] = 0.f;
#pragma unroll
        for (int c = 0; c < 4; c++) o[r][c] = 0.f;
    }

    for (int jt = 0; jt <= qt; jt++) {
        __syncthreads();   // prior reads of sK/sV/sP done; sQ visible after next sync
        // load K, V tiles
        const float4* k4 = (const float4*)(base_k + jt * 64 * Dv);
        const float4* v4 = (const float4*)(base_v + jt * 64 * Dv);
        for (int idx = tid; idx < 1024; idx += 256) {
            int r = idx >> 4, c = (idx & 15) << 2;
            float4 kv = k4[idx];
            float* dk = &sK[r * SSTR + c];
            dk[0] = kv.x; dk[1] = kv.y; dk[2] = kv.z; dk[3] = kv.w;
            float4 vv = v4[idx];
            float* dv = &sV[r * SSTR + c];
            dv[0] = vv.x; dv[1] = vv.y; dv[2] = vv.z; dv[3] = vv.w;
        }
        __syncthreads();

        // S = q K^T (already scaled)
        float s[4][4];
#pragma unroll
        for (int r = 0; r < 4; r++)
#pragma unroll
            for (int c = 0; c < 4; c++) s[r][c] = 0.f;
#pragma unroll 8
        for (int d = 0; d < 64; d++) {
            float qv[4], kv[4];
#pragma unroll
            for (int r = 0; r < 4; r++) qv[r] = sQ[(r0 + r) * SSTR + d];
#pragma unroll
            for (int c = 0; c < 4; c++) kv[c] = sK[(c0 + c) * SSTR + d];
#pragma unroll
            for (int r = 0; r < 4; r++)
#pragma unroll
                for (int c = 0; c < 4; c++) s[r][c] = fmaf(qv[r], kv[c], s[r][c]);
        }

        // causal mask on the diagonal tile (matches mask * -1e9 + softmax)
        if (jt == qt) {
#pragma unroll
            for (int r = 0; r < 4; r++)
#pragma unroll
                for (int c = 0; c < 4; c++)
                    if (c0 + c > r0 + r) s[r][c] -= NEG_BIG;
        }

        // online softmax (rows span 16 lanes of same ty)
#pragma unroll
        for (int r = 0; r < 4; r++) {
            float mx = fmaxf(fmaxf(s[r][0], s[r][1]), fmaxf(s[r][2], s[r][3]));
            mx = fmaxf(mx, __shfl_xor_sync(0xffffffffu, mx, 1, 16));
            mx = fmaxf(mx, __shfl_xor_sync(0xffffffffu, mx, 2, 16));
            mx = fmaxf(mx, __shfl_xor_sync(0xffffffffu, mx, 4, 16));
            mx = fmaxf(mx, __shfl_xor_sync(0xffffffffu, mx, 8, 16));
            float m_new = fmaxf(m_i[r], mx);
            float corr = __expf(m_i[r] - m_new);
            float p[4];
            float ls = 0.f;
#pragma unroll
            for (int c = 0; c < 4; c++) { p[c] = __expf(s[r][c] - m_new); ls += p[c]; }
            ls += __shfl_xor_sync(0xffffffffu, ls, 1, 16);
            ls += __shfl_xor_sync(0xffffffffu, ls, 2, 16);
            ls += __shfl_xor_sync(0xffffffffu, ls, 4, 16);
            ls += __shfl_xor_sync(0xffffffffu, ls, 8, 16);
            l_i[r] = l_i[r] * corr + ls;
            m_i[r] = m_new;
#pragma unroll
            for (int c = 0; c < 4; c++) o[r][c] *= corr;
#pragma unroll
            for (int c = 0; c < 4; c++) sP[(r0 + r) * SSTR + c0 + c] = p[c];
        }
        __syncthreads();

        // O += P V
#pragma unroll 8
        for (int j = 0; j < 64; j++) {
            float pv[4], vv[4];
#pragma unroll
            for (int r = 0; r < 4; r++) pv[r] = sP[(r0 + r) * SSTR + j];
#pragma unroll
            for (int c = 0; c < 4; c++) vv[c] = sV[j * SSTR + c0 + c];
#pragma unroll
            for (int r = 0; r < 4; r++)
#pragma unroll
                for (int c = 0; c < 4; c++) o[r][c] = fmaf(pv[r], vv[c], o[r][c]);
        }
    }

    // epilogue: normalize & store
    float* op = out + (size_t)bh * Sv * Dv + (size_t)(qt * 64) * Dv;
#pragma unroll
    for (int r = 0; r < 4; r++) {
        float inv = 1.f / l_i[r];
        float4 w;
        w.x = o[r][0] * inv; w.y = o[r][1] * inv;
        w.z = o[r][2] * inv; w.w = o[r][3] * inv;
        *(float4*)&op[(r0 + r) * 64 + c0] = w;
    }
}

// ---------------------------------------------------------------------------
extern "C" void kernel_launch(void* const* d_in, const int* in_sizes, int n_in,
                              void* d_out, int out_size) {
    const float* Hin = (const float*)d_in[0];
    const float* Hk  = (const float*)d_in[1];
    const float* Hvv = (const float*)d_in[2];
    const float* A   = (const float*)d_in[3];
    // d_in[4] = mask (causality implemented directly)
    const float* W   = (const float*)d_in[5];
    const float* b   = (const float*)d_in[6];
    const float* pw  = (const float*)d_in[7];
    const float* a   = (const float*)d_in[8];
    const float* ba  = (const float*)d_in[9];
    float* out = (float*)d_out;

    const int smem_bytes = SMEM_FLOATS * (int)sizeof(float);   // 66560
    cudaFuncSetAttribute(plga_attn, cudaFuncAttributeMaxDynamicSharedMemorySize,
                         smem_bytes);

    plga_stage_a<<<Bv * Hv_, 256>>>(A, W, b, pw, a, ba);
    plga_attn<<<dim3(Sv / 64, Bv * Hv_), 256, smem_bytes>>>(Hin, Hk, Hvv, out);
}

// round 4
// speedup vs baseline: 1.0021x; 1.0021x over previous
#include <cuda_runtime.h>
#include <math.h>

#define Bv 2
#define Hv_ 16
#define Sv 2048
#define Dv 64
#define EPS_ADJ 1e-9f
#define NEG_BIG 1e9f

// scratch for avAp [B*H, 64, 64]
__device__ float d_avAp[Bv * Hv_ * Dv * Dv];

// ---------------------------------------------------------------------------
// Stage A: avAp = a @ pow(iswiglu(W @ A + b) + eps, pw) + ba   per (b,h)
// One CTA per (b,h). 256 threads, 4x4 register tiles.
// ---------------------------------------------------------------------------
__global__ __launch_bounds__(256) void plga_stage_a(
    const float* __restrict__ A, const float* __restrict__ W,
    const float* __restrict__ b, const float* __restrict__ pw,
    const float* __restrict__ a, const float* __restrict__ ba)
{
    __shared__ float sL[64 * 64];   // left matrix (W, then a)
    __shared__ float sR[64 * 64];   // right matrix (A)
    __shared__ float sP[64 * 64];   // Ap

    int bh = blockIdx.x;
    int h = bh & (Hv_ - 1);
    int tid = threadIdx.x;
    int tx = tid & 15, ty = tid >> 4;
    int i0 = ty * 4, k0 = tx * 4;

    const float* Ab  = A  + bh * 4096;
    const float* Wh  = W  + h * 4096;
    const float* bhp = b  + h * 4096;
    const float* pwh = pw + h * 4096;
    const float* ah  = a  + h * 4096;
    const float* bah = ba + h * 4096;

    for (int idx = tid; idx < 4096; idx += 256) {
        sR[idx] = Ab[idx];
        sL[idx] = Wh[idx];
    }
    __syncthreads();

    float acc[4][4];
#pragma unroll
    for (int r = 0; r < 4; r++)
#pragma unroll
        for (int c = 0; c < 4; c++) acc[r][c] = 0.f;

#pragma unroll 4
    for (int j = 0; j < 64; j++) {
        float lv[4], rv[4];
#pragma unroll
        for (int r = 0; r < 4; r++) lv[r] = sL[(i0 + r) * 64 + j];
#pragma unroll
        for (int c = 0; c < 4; c++) rv[c] = sR[j * 64 + k0 + c];
#pragma unroll
        for (int r = 0; r < 4; r++)
#pragma unroll
            for (int c = 0; c < 4; c++) acc[r][c] = fmaf(lv[r], rv[c], acc[r][c]);
    }
    __syncthreads();

    // Ap = pow(iswiglu(x)+eps, pw)
#pragma unroll
    for (int r = 0; r < 4; r++)
#pragma unroll
        for (int c = 0; c < 4; c++) {
            int i = i0 + r, k = k0 + c;
            float x = acc[r][c] + bhp[i * 64 + k];
            float sig = 1.f / (1.f + expf(-x));
            float aw = x * x * sig + EPS_ADJ;   // x*silu(x) + eps, > 0
            sP[i * 64 + k] = powf(aw, pwh[i * 64 + k]);
        }

    // load 'a' into sL (all sL reads finished before previous sync)
    for (int idx = tid; idx < 4096; idx += 256) sL[idx] = ah[idx];
    __syncthreads();

#pragma unroll
    for (int r = 0; r < 4; r++)
#pragma unroll
        for (int c = 0; c < 4; c++) acc[r][c] = 0.f;

#pragma unroll 4
    for (int j = 0; j < 64; j++) {
        float lv[4], rv[4];
#pragma unroll
        for (int r = 0; r < 4; r++) lv[r] = sL[(i0 + r) * 64 + j];
#pragma unroll
        for (int c = 0; c < 4; c++) rv[c] = sP[j * 64 + k0 + c];
#pragma unroll
        for (int r = 0; r < 4; r++)
#pragma unroll
            for (int c = 0; c < 4; c++) acc[r][c] = fmaf(lv[r], rv[c], acc[r][c]);
    }

    float* outp = d_avAp + bh * 4096;
#pragma unroll
    for (int r = 0; r < 4; r++)
#pragma unroll
        for (int c = 0; c < 4; c++)
            outp[(i0 + r) * 64 + k0 + c] = acc[r][c] + bah[(i0 + r) * 64 + k0 + c];
}

// ---------------------------------------------------------------------------
// Attention: per CTA one 64-row q tile of one (b,h).
//   prologue: q = (Hin_tile @ avAp) * 1/sqrt(D)
//   loop over kv tiles 0..qt: S = q K^T, causal mask on diagonal,
//   online softmax, O += P V. 256 threads, 4x4 fragments, stride-65 smem.
// ---------------------------------------------------------------------------
#define SSTR 65
#define SMEM_FLOATS (4 * 64 * SSTR)

__global__ __launch_bounds__(256) void plga_attn(
    const float* __restrict__ Hin, const float* __restrict__ Hk,
    const float* __restrict__ Hvv, float* __restrict__ out)
{
    extern __shared__ float smem[];
    float* sQ = smem;                  // [64][65]
    float* sK = smem + 64 * SSTR;      // [64][65] (avAp in prologue)
    float* sV = smem + 2 * 64 * SSTR;  // [64][65] (Hin tile in prologue)
    float* sP = smem + 3 * 64 * SSTR;  // [64][65]

    int bh = blockIdx.y;
    int qt = blockIdx.x;
    int tid = threadIdx.x;
    int tx = tid & 15, ty = tid >> 4;
    int r0 = ty * 4, c0 = tx * 4;

    const float* base_in = Hin + (size_t)bh * Sv * Dv;
    const float* base_k  = Hk  + (size_t)bh * Sv * Dv;
    const float* base_v  = Hvv + (size_t)bh * Sv * Dv;

    // ---- prologue: avAp -> sK, Hin tile -> sV ----
    {
        const float4* a4 = (const float4*)(d_avAp + bh * 4096);
        const float4* h4 = (const float4*)(base_in + qt * 64 * Dv);
        for (int idx = tid; idx < 1024; idx += 256) {
            int r = idx >> 4, c = (idx & 15) << 2;
            float4 v1 = a4[idx];
            float* d1 = &sK[r * SSTR + c];
            d1[0] = v1.x; d1[1] = v1.y; d1[2] = v1.z; d1[3] = v1.w;
            float4 v2 = h4[idx];
            float* d2 = &sV[r * SSTR + c];
            d2[0] = v2.x; d2[1] = v2.y; d2[2] = v2.z; d2[3] = v2.w;
        }
    }
    __syncthreads();
    {
        float acc[4][4];
#pragma unroll
        for (int r = 0; r < 4; r++)
#pragma unroll
            for (int c = 0; c < 4; c++) acc[r][c] = 0.f;
#pragma unroll 8
        for (int i = 0; i < 64; i++) {
            float hvr[4], avv[4];
#pragma unroll
            for (int r = 0; r < 4; r++) hvr[r] = sV[(r0 + r) * SSTR + i];
#pragma unroll
            for (int c = 0; c < 4; c++) avv[c] = sK[i * SSTR + c0 + c];
#pragma unroll
            for (int r = 0; r < 4; r++)
#pragma unroll
                for (int c = 0; c < 4; c++) acc[r][c] = fmaf(hvr[r], avv[c], acc[r][c]);
        }
        // write scaled q fragments (only our own cells; visible after next sync)
#pragma unroll
        for (int r = 0; r < 4; r++)
#pragma unroll
            for (int c = 0; c < 4; c++)
                sQ[(r0 + r) * SSTR + c0 + c] = acc[r][c] * 0.125f;  // 1/sqrt(64)
    }

    float m_i[4], l_i[4], o[4][4];
#pragma unroll
    for (int r = 0; r < 4; r++) {
        m_i[r] = -1e30f;
        l_i[r] = 0.f;
#pragma unroll
        for (int c = 0; c < 4; c++) o[r][c] = 0.f;
    }

    for (int jt = 0; jt <= qt; jt++) {
        __syncthreads();   // prior reads of sK/sV/sP done; sQ visible after next sync
        // load K, V tiles
        const float4* k4 = (const float4*)(base_k + jt * 64 * Dv);
        const float4* v4 = (const float4*)(base_v + jt * 64 * Dv);
        for (int idx = tid; idx < 1024; idx += 256) {
            int r = idx >> 4, c = (idx & 15) << 2;
            float4 kv = k4[idx];
            float* dk = &sK[r * SSTR + c];
            dk[0] = kv.x; dk[1] = kv.y; dk[2] = kv.z; dk[3] = kv.w;
            float4 vv = v4[idx];
            float* dv = &sV[r * SSTR + c];
            dv[0] = vv.x; dv[1] = vv.y; dv[2] = vv.z; dv[3] = vv.w;
        }
        __syncthreads();

        // S = q K^T (already scaled)
        float s[4][4];
#pragma unroll
        for (int r = 0; r < 4; r++)
#pragma unroll
            for (int c = 0; c < 4; c++) s[r][c] = 0.f;
#pragma unroll 8
        for (int d = 0; d < 64; d++) {
            float qv[4], kv[4];
#pragma unroll
            for (int r = 0; r < 4; r++) qv[r] = sQ[(r0 + r) * SSTR + d];
#pragma unroll
            for (int c = 0; c < 4; c++) kv[c] = sK[(c0 + c) * SSTR + d];
#pragma unroll
            for (int r = 0; r < 4; r++)
#pragma unroll
                for (int c = 0; c < 4; c++) s[r][c] = fmaf(qv[r], kv[c], s[r][c]);
        }

        // causal mask on the diagonal tile (matches mask * -1e9 + softmax)
        if (jt == qt) {
#pragma unroll
            for (int r = 0; r < 4; r++)
#pragma unroll
                for (int c = 0; c < 4; c++)
                    if (c0 + c > r0 + r) s[r][c] -= NEG_BIG;
        }

        // online softmax (rows span 16 lanes of same ty)
#pragma unroll
        for (int r = 0; r < 4; r++) {
            float mx = fmaxf(fmaxf(s[r][0], s[r][1]), fmaxf(s[r][2], s[r][3]));
            mx = fmaxf(mx, __shfl_xor_sync(0xffffffffu, mx, 1, 16));
            mx = fmaxf(mx, __shfl_xor_sync(0xffffffffu, mx, 2, 16));
            mx = fmaxf(mx, __shfl_xor_sync(0xffffffffu, mx, 4, 16));
            mx = fmaxf(mx, __shfl_xor_sync(0xffffffffu, mx, 8, 16));
            float m_new = fmaxf(m_i[r], mx);
            float corr = __expf(m_i[r] - m_new);
            float p[4];
            float ls = 0.f;
#pragma unroll
            for (int c = 0; c < 4; c++) { p[c] = __expf(s[r][c] - m_new); ls += p[c]; }
            ls += __shfl_xor_sync(0xffffffffu, ls, 1, 16);
            ls += __shfl_xor_sync(0xffffffffu, ls, 2, 16);
            ls += __shfl_xor_sync(0xffffffffu, ls, 4, 16);
            ls += __shfl_xor_sync(0xffffffffu, ls, 8, 16);
            l_i[r] = l_i[r] * corr + ls;
            m_i[r] = m_new;
#pragma unroll
            for (int c = 0; c < 4; c++) o[r][c] *= corr;
#pragma unroll
            for (int c = 0; c < 4; c++) sP[(r0 + r) * SSTR + c0 + c] = p[c];
        }
        __syncthreads();

        // O += P V
#pragma unroll 8
        for (int j = 0; j < 64; j++) {
            float pv[4], vv[4];
#pragma unroll
            for (int r = 0; r < 4; r++) pv[r] = sP[(r0 + r) * SSTR + j];
#pragma unroll
            for (int c = 0; c < 4; c++) vv[c] = sV[j * SSTR + c0 + c];
#pragma unroll
            for (int r = 0; r < 4; r++)
#pragma unroll
                for (int c = 0; c < 4; c++) o[r][c] = fmaf(pv[r], vv[c], o[r][c]);
        }
    }

    // epilogue: normalize & store
    float* op = out + (size_t)bh * Sv * Dv + (size_t)(qt * 64) * Dv;
#pragma unroll
    for (int r = 0; r < 4; r++) {
        float inv = 1.f / l_i[r];
        float4 w;
        w.x = o[r][0] * inv; w.y = o[r][1] * inv;
        w.z = o[r][2] * inv; w.w = o[r][3] * inv;
        *(float4*)&op[(r0 + r) * 64 + c0] = w;
    }
}

// ---------------------------------------------------------------------------
extern "C" void kernel_launch(void* const* d_in, const int* in_sizes, int n_in,
                              void* d_out, int out_size) {
    const float* Hin = (const float*)d_in[0];
    const float* Hk  = (const float*)d_in[1];
    const float* Hvv = (const float*)d_in[2];
    const float* A   = (const float*)d_in[3];
    // d_in[4] = mask (causality implemented directly)
    const float* W   = (const float*)d_in[5];
    const float* b   = (const float*)d_in[6];
    const float* pw  = (const float*)d_in[7];
    const float* a   = (const float*)d_in[8];
    const float* ba  = (const float*)d_in[9];
    float* out = (float*)d_out;

    const int smem_bytes = SMEM_FLOATS * (int)sizeof(float);   // 66560
    cudaFuncSetAttribute(plga_attn, cudaFuncAttributeMaxDynamicSharedMemorySize,
                         smem_bytes);

    plga_stage_a<<<Bv * Hv_, 256>>>(A, W, b, pw, a, ba);
    plga_attn<<<dim3(Sv / 64, Bv * Hv_), 256, smem_bytes>>>(Hin, Hk, Hvv, out);
}

// round 5
// speedup vs baseline: 1.0113x; 1.0092x over previous
#include <cuda_runtime.h>
#include <math.h>

#define Bv 2
#define Hv_ 16
#define Sv 2048
#define Dv 64
#define EPS_ADJ 1e-9f
#define NEG_BIG 1e9f

// scratch for avAp [B*H, 64, 64]
__device__ float d_avAp[Bv * Hv_ * Dv * Dv];

// ---------------------------------------------------------------------------
// Stage A: avAp = a @ pow(iswiglu(W @ A + b) + eps, pw) + ba   per (b,h)
// One CTA per (b,h). 256 threads, 4x4 register tiles.
// ---------------------------------------------------------------------------
__global__ __launch_bounds__(256) void plga_stage_a(
    const float* __restrict__ A, const float* __restrict__ W,
    const float* __restrict__ b, const float* __restrict__ pw,
    const float* __restrict__ a, const float* __restrict__ ba)
{
    __shared__ float sL[64 * 64];   // left matrix (W, then a)
    __shared__ float sR[64 * 64];   // right matrix (A)
    __shared__ float sP[64 * 64];   // Ap

    int bh = blockIdx.x;
    int h = bh & (Hv_ - 1);
    int tid = threadIdx.x;
    int tx = tid & 15, ty = tid >> 4;
    int i0 = ty * 4, k0 = tx * 4;

    const float* Ab  = A  + bh * 4096;
    const float* Wh  = W  + h * 4096;
    const float* bhp = b  + h * 4096;
    const float* pwh = pw + h * 4096;
    const float* ah  = a  + h * 4096;
    const float* bah = ba + h * 4096;

    for (int idx = tid; idx < 4096; idx += 256) {
        sR[idx] = Ab[idx];
        sL[idx] = Wh[idx];
    }
    __syncthreads();

    float acc[4][4];
#pragma unroll
    for (int r = 0; r < 4; r++)
#pragma unroll
        for (int c = 0; c < 4; c++) acc[r][c] = 0.f;

#pragma unroll 4
    for (int j = 0; j < 64; j++) {
        float lv[4], rv[4];
#pragma unroll
        for (int r = 0; r < 4; r++) lv[r] = sL[(i0 + r) * 64 + j];
#pragma unroll
        for (int c = 0; c < 4; c++) rv[c] = sR[j * 64 + k0 + c];
#pragma unroll
        for (int r = 0; r < 4; r++)
#pragma unroll
            for (int c = 0; c < 4; c++) acc[r][c] = fmaf(lv[r], rv[c], acc[r][c]);
    }
    __syncthreads();

    // Ap = pow(iswiglu(x)+eps, pw)
#pragma unroll
    for (int r = 0; r < 4; r++)
#pragma unroll
        for (int c = 0; c < 4; c++) {
            int i = i0 + r, k = k0 + c;
            float x = acc[r][c] + bhp[i * 64 + k];
            float sig = 1.f / (1.f + expf(-x));
            float aw = x * x * sig + EPS_ADJ;   // x*silu(x) + eps, > 0
            sP[i * 64 + k] = powf(aw, pwh[i * 64 + k]);
        }

    // load 'a' into sL (all sL reads finished before previous sync)
    for (int idx = tid; idx < 4096; idx += 256) sL[idx] = ah[idx];
    __syncthreads();

#pragma unroll
    for (int r = 0; r < 4; r++)
#pragma unroll
        for (int c = 0; c < 4; c++) acc[r][c] = 0.f;

#pragma unroll 4
    for (int j = 0; j < 64; j++) {
        float lv[4], rv[4];
#pragma unroll
        for (int r = 0; r < 4; r++) lv[r] = sL[(i0 + r) * 64 + j];
#pragma unroll
        for (int c = 0; c < 4; c++) rv[c] = sP[j * 64 + k0 + c];
#pragma unroll
        for (int r = 0; r < 4; r++)
#pragma unroll
            for (int c = 0; c < 4; c++) acc[r][c] = fmaf(lv[r], rv[c], acc[r][c]);
    }

    float* outp = d_avAp + bh * 4096;
#pragma unroll
    for (int r = 0; r < 4; r++)
#pragma unroll
        for (int c = 0; c < 4; c++)
            outp[(i0 + r) * 64 + k0 + c] = acc[r][c] + bah[(i0 + r) * 64 + k0 + c];
}

// ---------------------------------------------------------------------------
// Attention: per CTA one 64-row q tile of one (b,h).
//   prologue: q = (Hin_tile @ avAp) * 1/sqrt(D)
//   loop over kv tiles 0..qt: S = q K^T, causal mask on diagonal,
//   online softmax, O += P V. 256 threads, 4x4 fragments, stride-65 smem.
// ---------------------------------------------------------------------------
#define SSTR 65
#define SMEM_FLOATS (4 * 64 * SSTR)

__global__ __launch_bounds__(256) void plga_attn(
    const float* __restrict__ Hin, const float* __restrict__ Hk,
    const float* __restrict__ Hvv, float* __restrict__ out)
{
    extern __shared__ float smem[];
    float* sQ = smem;                  // [64][65]
    float* sK = smem + 64 * SSTR;      // [64][65] (avAp in prologue)
    float* sV = smem + 2 * 64 * SSTR;  // [64][65] (Hin tile in prologue)
    float* sP = smem + 3 * 64 * SSTR;  // [64][65]

    int bh = blockIdx.y;
    int qt = blockIdx.x;
    int tid = threadIdx.x;
    int tx = tid & 15, ty = tid >> 4;
    int r0 = ty * 4, c0 = tx * 4;

    const float* base_in = Hin + (size_t)bh * Sv * Dv;
    const float* base_k  = Hk  + (size_t)bh * Sv * Dv;
    const float* base_v  = Hvv + (size_t)bh * Sv * Dv;

    // ---- prologue: avAp -> sK, Hin tile -> sV ----
    {
        const float4* a4 = (const float4*)(d_avAp + bh * 4096);
        const float4* h4 = (const float4*)(base_in + qt * 64 * Dv);
        for (int idx = tid; idx < 1024; idx += 256) {
            int r = idx >> 4, c = (idx & 15) << 2;
            float4 v1 = a4[idx];
            float* d1 = &sK[r * SSTR + c];
            d1[0] = v1.x; d1[1] = v1.y; d1[2] = v1.z; d1[3] = v1.w;
            float4 v2 = h4[idx];
            float* d2 = &sV[r * SSTR + c];
            d2[0] = v2.x; d2[1] = v2.y; d2[2] = v2.z; d2[3] = v2.w;
        }
    }
    __syncthreads();
    {
        float acc[4][4];
#pragma unroll
        for (int r = 0; r < 4; r++)
#pragma unroll
            for (int c = 0; c < 4; c++) acc[r][c] = 0.f;
#pragma unroll 8
        for (int i = 0; i < 64; i++) {
            float hvr[4], avv[4];
#pragma unroll
            for (int r = 0; r < 4; r++) hvr[r] = sV[(r0 + r) * SSTR + i];
#pragma unroll
            for (int c = 0; c < 4; c++) avv[c] = sK[i * SSTR + c0 + c];
#pragma unroll
            for (int r = 0; r < 4; r++)
#pragma unroll
                for (int c = 0; c < 4; c++) acc[r][c] = fmaf(hvr[r], avv[c], acc[r][c]);
        }
        // write scaled q fragments (only our own cells; visible after next sync)
#pragma unroll
        for (int r = 0; r < 4; r++)
#pragma unroll
            for (int c = 0; c < 4; c++)
                sQ[(r0 + r) * SSTR + c0 + c] = acc[r][c] * 0.125f;  // 1/sqrt(64)
    }

    float m_i[4], l_i[4], o[4][4];
#pragma unroll
    for (int r = 0; r < 4; r++) {
        m_i[r] = -1e30f;
        l_i[r] = 0.f;
#pragma unroll
        for (int c = 0; c < 4; c++) o[r][c] = 0.f;
    }

    for (int jt = 0; jt <= qt; jt++) {
        __syncthreads();   // prior reads of sK/sV/sP done; sQ visible after next sync
        // load K, V tiles
        const float4* k4 = (const float4*)(base_k + jt * 64 * Dv);
        const float4* v4 = (const float4*)(base_v + jt * 64 * Dv);
        for (int idx = tid; idx < 1024; idx += 256) {
            int r = idx >> 4, c = (idx & 15) << 2;
            float4 kv = k4[idx];
            float* dk = &sK[r * SSTR + c];
            dk[0] = kv.x; dk[1] = kv.y; dk[2] = kv.z; dk[3] = kv.w;
            float4 vv = v4[idx];
            float* dv = &sV[r * SSTR + c];
            dv[0] = vv.x; dv[1] = vv.y; dv[2] = vv.z; dv[3] = vv.w;
        }
        __syncthreads();

        // S = q K^T (already scaled)
        float s[4][4];
#pragma unroll
        for (int r = 0; r < 4; r++)
#pragma unroll
            for (int c = 0; c < 4; c++) s[r][c] = 0.f;
#pragma unroll 8
        for (int d = 0; d < 64; d++) {
            float qv[4], kv[4];
#pragma unroll
            for (int r = 0; r < 4; r++) qv[r] = sQ[(r0 + r) * SSTR + d];
#pragma unroll
            for (int c = 0; c < 4; c++) kv[c] = sK[(c0 + c) * SSTR + d];
#pragma unroll
            for (int r = 0; r < 4; r++)
#pragma unroll
                for (int c = 0; c < 4; c++) s[r][c] = fmaf(qv[r], kv[c], s[r][c]);
        }

        // causal mask on the diagonal tile (matches mask * -1e9 + softmax)
        if (jt == qt) {
#pragma unroll
            for (int r = 0; r < 4; r++)
#pragma unroll
                for (int c = 0; c < 4; c++)
                    if (c0 + c > r0 + r) s[r][c] -= NEG_BIG;
        }

        // online softmax (rows span 16 lanes of same ty)
#pragma unroll
        for (int r = 0; r < 4; r++) {
            float mx = fmaxf(fmaxf(s[r][0], s[r][1]), fmaxf(s[r][2], s[r][3]));
            mx = fmaxf(mx, __shfl_xor_sync(0xffffffffu, mx, 1, 16));
            mx = fmaxf(mx, __shfl_xor_sync(0xffffffffu, mx, 2, 16));
            mx = fmaxf(mx, __shfl_xor_sync(0xffffffffu, mx, 4, 16));
            mx = fmaxf(mx, __shfl_xor_sync(0xffffffffu, mx, 8, 16));
            float m_new = fmaxf(m_i[r], mx);
            float corr = __expf(m_i[r] - m_new);
            float p[4];
            float ls = 0.f;
#pragma unroll
            for (int c = 0; c < 4; c++) { p[c] = __expf(s[r][c] - m_new); ls += p[c]; }
            ls += __shfl_xor_sync(0xffffffffu, ls, 1, 16);
            ls += __shfl_xor_sync(0xffffffffu, ls, 2, 16);
            ls += __shfl_xor_sync(0xffffffffu, ls, 4, 16);
            ls += __shfl_xor_sync(0xffffffffu, ls, 8, 16);
            l_i[r] = l_i[r] * corr + ls;
            m_i[r] = m_new;
#pragma unroll
            for (int c = 0; c < 4; c++) o[r][c] *= corr;
#pragma unroll
            for (int c = 0; c < 4; c++) sP[(r0 + r) * SSTR + c0 + c] = p[c];
        }
        __syncthreads();

        // O += P V
#pragma unroll 8
        for (int j = 0; j < 64; j++) {
            float pv[4], vv[4];
#pragma unroll
            for (int r = 0; r < 4; r++) pv[r] = sP[(r0 + r) * SSTR + j];
#pragma unroll
            for (int c = 0; c < 4; c++) vv[c] = sV[j * SSTR + c0 + c];
#pragma unroll
            for (int r = 0; r < 4; r++)
#pragma unroll
                for (int c = 0; c < 4; c++) o[r][c] = fmaf(pv[r], vv[c], o[r][c]);
        }
    }

    // epilogue: normalize & store
    float* op = out + (size_t)bh * Sv * Dv + (size_t)(qt * 64) * Dv;
#pragma unroll
    for (int r = 0; r < 4; r++) {
        float inv = 1.f / l_i[r];
        float4 w;
        w.x = o[r][0] * inv; w.y = o[r][1] * inv;
        w.z = o[r][2] * inv; w.w = o[r][3] * inv;
        *(float4*)&op[(r0 + r) * 64 + c0] = w;
    }
}

// ---------------------------------------------------------------------------
extern "C" void kernel_launch(void* const* d_in, const int* in_sizes, int n_in,
                              void* d_out, int out_size) {
    const float* Hin = (const float*)d_in[0];
    const float* Hk  = (const float*)d_in[1];
    const float* Hvv = (const float*)d_in[2];
    const float* A   = (const float*)d_in[3];
    // d_in[4] = mask (causality implemented directly)
    const float* W   = (const float*)d_in[5];
    const float* b   = (const float*)d_in[6];
    const float* pw  = (const float*)d_in[7];
    const float* a   = (const float*)d_in[8];
    const float* ba  = (const float*)d_in[9];
    float* out = (float*)d_out;

    const int smem_bytes = SMEM_FLOATS * (int)sizeof(float);   // 66560
    cudaFuncSetAttribute(plga_attn, cudaFuncAttributeMaxDynamicSharedMemorySize,
                         smem_bytes);

    plga_stage_a<<<Bv * Hv_, 256>>>(A, W, b, pw, a, ba);
    plga_attn<<<dim3(Sv / 64, Bv * Hv_), 256, smem_bytes>>>(Hin, Hk, Hvv, out);
}